// round 9
// baseline (speedup 1.0000x reference)
#include <cuda_runtime.h>
#include <cuda_bf16.h>
#include <cstdint>

#define NN 100000
#define NE 1000000
#define F  64
#define NPB 24   // nodes per combine block

// Scratch (allocation-free rules: __device__ globals). Referenced directly
// inside kernels — no cudaGetSymbolAddress, no host-side symbol lookups.
// 16B alignment guaranteed explicitly: these are accessed via float4.
__device__ __align__(16) float g_sum[(size_t)NN * F];  // 25.6 MB neighbor-sum
__device__ __align__(16) float g_h[(size_t)NN * F];    // 25.6 MB hidden acts
__device__ int g_cnt[NN];                               // in-degree

// ---------------------------------------------------------------------------
// Zero the accumulator (and degree counts on the first pass)
// ---------------------------------------------------------------------------
__global__ void zero_kernel(int zero_cnt) {
    int i = blockIdx.x * blockDim.x + threadIdx.x;
    if (i < NN * F / 4)
        reinterpret_cast<float4*>(g_sum)[i] = make_float4(0.f, 0.f, 0.f, 0.f);
    if (zero_cnt && i < NN) g_cnt[i] = 0;
}

// ---------------------------------------------------------------------------
// Edge scatter: 16 threads per edge, each owns one float4 (16B) of the 256B
// feature row. Gather feat[src] (L2-resident), accumulate into g_sum[dst]
// with 4 plain scalar atomicAdd (REDG.ADD.F32 — no return, fire-and-forget).
// Indices are int32 (harness dtype mapping: int -> const int*).
// ---------------------------------------------------------------------------
__global__ void scatter_kernel(const float* __restrict__ x,
                               const int* __restrict__ src,
                               const int* __restrict__ dst,
                               int layer) {
    const float* __restrict__ feat = (layer == 0) ? x : (const float*)g_h;

    int t = blockIdx.x * blockDim.x + threadIdx.x;
    int e = t >> 4;
    int part = t & 15;
    if (e >= NE) return;

    int s = __ldg(&src[e]);
    int d = __ldg(&dst[e]);
    // Bounds guard: if the index dtype assumption is ever wrong, fail with a
    // visible rel_err, not a device trap.
    if ((unsigned)s >= NN || (unsigned)d >= NN) return;

    if (layer == 0 && part == 0) atomicAdd(&g_cnt[d], 1);

    const float4 v = *reinterpret_cast<const float4*>(feat + (size_t)s * F + part * 4);
    float* p0 = g_sum + (size_t)d * F + part * 4;
    atomicAdd(p0 + 0, v.x);
    atomicAdd(p0 + 1, v.y);
    atomicAdd(p0 + 2, v.z);
    atomicAdd(p0 + 3, v.w);
}

// ---------------------------------------------------------------------------
// Combine: out[n] = (g_sum[n]/max(cnt,1)) @ Wl^T + b + feat[n] @ Wr^T (+relu)
// Block (64, 4) = 256 threads, NPB=24 nodes per block, 6 accumulators/thread.
// Weights staged transposed in smem with stride-65 padding (conflict-free).
// ---------------------------------------------------------------------------
__global__ void combine_kernel(const float* __restrict__ x,
                               const float* __restrict__ Wl,   // [64,64] [o][k]
                               const float* __restrict__ bl,   // [64]
                               const float* __restrict__ Wr,   // [64,64]
                               float* __restrict__ out_param,
                               int layer) {
    const float* __restrict__ feat = (layer == 0) ? x : (const float*)g_h;
    float* __restrict__ out        = (layer == 0) ? (float*)g_h : out_param;
    const int relu = (layer == 0);

    __shared__ float sWl[64 * 65];
    __shared__ float sWr[64 * 65];
    __shared__ float sB[64];
    __shared__ float sAgg[NPB][64];
    __shared__ float sX[NPB][64];

    const int tid = threadIdx.y * 64 + threadIdx.x;

    // Stage weights transposed: sW[k*65 + o] = W[o*64 + k]
    #pragma unroll
    for (int i = tid; i < 4096; i += 256) {
        int o = i >> 6, k = i & 63;
        sWl[k * 65 + o] = Wl[i];
        sWr[k * 65 + o] = Wr[i];
    }
    if (tid < 64) sB[tid] = bl[tid];

    const int node0 = blockIdx.x * NPB;

    // Stage node tiles: mean-normalized aggregate + root features
    for (int i = tid; i < NPB * 64; i += 256) {
        int r = i >> 6, c = i & 63;
        int n = node0 + r;
        if (n < NN) {
            float inv = 1.0f / fmaxf((float)g_cnt[n], 1.0f);
            sAgg[r][c] = g_sum[(size_t)n * F + c] * inv;
            sX[r][c]   = feat[(size_t)n * F + c];
        } else {
            sAgg[r][c] = 0.0f;
            sX[r][c]   = 0.0f;
        }
    }
    __syncthreads();

    const int ox = threadIdx.x;   // output feature index
    float acc[6];
    #pragma unroll
    for (int r = 0; r < 6; r++) acc[r] = sB[ox];

    #pragma unroll 8
    for (int k = 0; k < 64; k++) {
        float wl = sWl[k * 65 + ox];
        float wr = sWr[k * 65 + ox];
        #pragma unroll
        for (int r = 0; r < 6; r++) {
            int row = threadIdx.y + r * 4;
            acc[r] += sAgg[row][k] * wl + sX[row][k] * wr;
        }
    }

    #pragma unroll
    for (int r = 0; r < 6; r++) {
        int row = threadIdx.y + r * 4;
        int n = node0 + row;
        if (n < NN) {
            float v = acc[r];
            if (relu) v = fmaxf(v, 0.0f);
            out[(size_t)n * F + ox] = v;
        }
    }
}

// ---------------------------------------------------------------------------
// Launch sequence (graph-capturable: kernel launches only, default stream,
// no host CUDA API calls besides launches)
// ---------------------------------------------------------------------------
extern "C" void kernel_launch(void* const* d_in, const int* in_sizes, int n_in,
                              void* d_out, int out_size) {
    const float* x   = (const float*)d_in[0];
    const int*   ei  = (const int*)d_in[1];     // edge_index as int32 [2, E]
    const float* W1l = (const float*)d_in[2];
    const float* b1  = (const float*)d_in[3];
    const float* W1r = (const float*)d_in[4];
    const float* W2l = (const float*)d_in[5];
    const float* b2  = (const float*)d_in[6];
    const float* W2r = (const float*)d_in[7];
    float*       out = (float*)d_out;

    const int* src = ei;        // edge_index[0]
    const int* dst = ei + NE;   // edge_index[1]

    const int zeroBlocks    = (NN * F / 4 + 255) / 256;
    const int scatterBlocks = (NE * 16 + 255) / 256;
    const int combineBlocks = (NN + NPB - 1) / NPB;

    // Layer 1: aggregate x -> g_sum, combine -> g_h (relu)
    zero_kernel<<<zeroBlocks, 256>>>(1);
    scatter_kernel<<<scatterBlocks, 256>>>(x, src, dst, 0);
    combine_kernel<<<combineBlocks, dim3(64, 4)>>>(x, W1l, b1, W1r, nullptr, 0);

    // Layer 2: aggregate g_h -> g_sum, combine -> out
    zero_kernel<<<zeroBlocks, 256>>>(0);
    scatter_kernel<<<scatterBlocks, 256>>>(x, src, dst, 1);
    combine_kernel<<<combineBlocks, dim3(64, 4)>>>(x, W2l, b2, W2r, out, 1);
}

// round 13
// speedup vs baseline: 1.2412x; 1.2412x over previous
#include <cuda_runtime.h>
#include <cuda_bf16.h>
#include <cstdint>

#define NN 100000
#define NE 1000000
#define F  64
#define NPB 24   // nodes per combine block (8 warps x 3 nodes)

// Scratch (__device__ globals; allocation-free rules)
__device__ __align__(16) float g_h[(size_t)NN * F];  // hidden activations
__device__ int g_cnt[NN];          // in-degree
__device__ int g_fill[NN];         // CSR fill cursors
__device__ int g_rowptr[NN + 1];   // CSR row pointers (dst-bucketed)
__device__ int g_eidx[NE];         // CSR column indices (src node ids)

// ---------------------------------------------------------------------------
// Zero degree counters and fill cursors
// ---------------------------------------------------------------------------
__global__ void init_kernel() {
    int i = blockIdx.x * blockDim.x + threadIdx.x;
    if (i < NN) { g_cnt[i] = 0; g_fill[i] = 0; }
}

// ---------------------------------------------------------------------------
// In-degree count: one thread per edge
// ---------------------------------------------------------------------------
__global__ void degree_kernel(const int* __restrict__ dst) {
    int e = blockIdx.x * blockDim.x + threadIdx.x;
    if (e >= NE) return;
    int d = __ldg(&dst[e]);
    if ((unsigned)d < NN) atomicAdd(&g_cnt[d], 1);
}

// ---------------------------------------------------------------------------
// Exclusive prefix scan of g_cnt -> g_rowptr. Single block, 1024 threads,
// 100 elements per thread (1024*100 >= NN). Two passes over g_cnt + a
// Hillis-Steele scan of the 1024 partials (safe read-sync-write-sync form).
// ---------------------------------------------------------------------------
__global__ void scan_kernel() {
    __shared__ int spart[1024];
    const int t = threadIdx.x;
    const int CH = 100;
    const int base = t * CH;

    int sum = 0;
    #pragma unroll 4
    for (int i = 0; i < CH; i++) {
        int idx = base + i;
        sum += (idx < NN) ? g_cnt[idx] : 0;
    }
    spart[t] = sum;
    __syncthreads();

    for (int off = 1; off < 1024; off <<= 1) {
        int v = (t >= off) ? spart[t - off] : 0;
        __syncthreads();
        spart[t] += v;
        __syncthreads();
    }
    int run = (t == 0) ? 0 : spart[t - 1];   // exclusive prefix

    for (int i = 0; i < CH; i++) {
        int idx = base + i;
        if (idx < NN) { g_rowptr[idx] = run; run += g_cnt[idx]; }
    }
    if (t == 1023) g_rowptr[NN] = run;       // = total edge count
}

// ---------------------------------------------------------------------------
// CSR fill: bucket each edge's src under its dst
// ---------------------------------------------------------------------------
__global__ void fill_kernel(const int* __restrict__ src,
                            const int* __restrict__ dst) {
    int e = blockIdx.x * blockDim.x + threadIdx.x;
    if (e >= NE) return;
    int s = __ldg(&src[e]);
    int d = __ldg(&dst[e]);
    if ((unsigned)s >= NN || (unsigned)d >= NN) return;
    int pos = g_rowptr[d] + atomicAdd(&g_fill[d], 1);
    g_eidx[pos] = s;
}

// ---------------------------------------------------------------------------
// Fused gather + combine:
//   agg[n] = mean_{s in CSR[n]} feat[s]
//   out[n] = agg[n] @ Wl^T + b + feat[n] @ Wr^T   (+relu for layer 0)
// Block = (64,4) = 256 threads = 8 warps; NPB=24 nodes (3 per warp).
// Gather: lane owns dims (2*lane, 2*lane+1) as float2 -> each neighbor row is
// one coalesced 256B warp read from L2. 2-way neighbor unroll for MLP.
// ---------------------------------------------------------------------------
__global__ void combine_kernel(const float* __restrict__ x,
                               const float* __restrict__ Wl,   // [64,64] [o][k]
                               const float* __restrict__ bl,   // [64]
                               const float* __restrict__ Wr,   // [64,64]
                               float* __restrict__ out_param,
                               int layer) {
    const float* __restrict__ feat = (layer == 0) ? x : (const float*)g_h;
    float* __restrict__ out        = (layer == 0) ? (float*)g_h : out_param;
    const int relu = (layer == 0);

    __shared__ float sWl[64 * 65];
    __shared__ float sWr[64 * 65];
    __shared__ float sB[64];
    __shared__ float sAgg[NPB][64];
    __shared__ float sX[NPB][64];

    const int tid = threadIdx.y * 64 + threadIdx.x;
    const int node0 = blockIdx.x * NPB;

    // Stage weights transposed: sW[k*65 + o] = W[o*64 + k]
    #pragma unroll
    for (int i = tid; i < 4096; i += 256) {
        int o = i >> 6, k = i & 63;
        sWl[k * 65 + o] = Wl[i];
        sWr[k * 65 + o] = Wr[i];
    }
    if (tid < 64) sB[tid] = bl[tid];

    // Stage root features
    for (int i = tid; i < NPB * 64; i += 256) {
        int r = i >> 6, c = i & 63;
        int n = node0 + r;
        sX[r][c] = (n < NN) ? feat[(size_t)n * F + c] : 0.0f;
    }

    // Gather phase: warp w handles nodes node0 + 3w .. 3w+2
    {
        const int warp = tid >> 5;
        const int lane = tid & 31;
        const float2* __restrict__ fp = reinterpret_cast<const float2*>(feat);

        #pragma unroll
        for (int i = 0; i < 3; i++) {
            int r = warp * 3 + i;
            int n = node0 + r;
            float ax = 0.0f, ay = 0.0f;
            if (n < NN) {
                int beg = g_rowptr[n];
                int end = g_rowptr[n + 1];
                int j = beg;
                for (; j + 1 < end; j += 2) {
                    int i0 = __ldg(&g_eidx[j]);
                    int i1 = __ldg(&g_eidx[j + 1]);
                    float2 v0 = fp[(size_t)i0 * 32 + lane];
                    float2 v1 = fp[(size_t)i1 * 32 + lane];
                    ax += v0.x + v1.x;
                    ay += v0.y + v1.y;
                }
                if (j < end) {
                    int i0 = __ldg(&g_eidx[j]);
                    float2 v0 = fp[(size_t)i0 * 32 + lane];
                    ax += v0.x;
                    ay += v0.y;
                }
                float inv = 1.0f / fmaxf((float)(end - beg), 1.0f);
                ax *= inv; ay *= inv;
            }
            sAgg[r][lane * 2 + 0] = ax;
            sAgg[r][lane * 2 + 1] = ay;
        }
    }
    __syncthreads();

    // GEMM phase
    const int ox = threadIdx.x;
    float acc[6];
    #pragma unroll
    for (int r = 0; r < 6; r++) acc[r] = sB[ox];

    #pragma unroll 8
    for (int k = 0; k < 64; k++) {
        float wl = sWl[k * 65 + ox];
        float wr = sWr[k * 65 + ox];
        #pragma unroll
        for (int r = 0; r < 6; r++) {
            int row = threadIdx.y + r * 4;
            acc[r] += sAgg[row][k] * wl + sX[row][k] * wr;
        }
    }

    #pragma unroll
    for (int r = 0; r < 6; r++) {
        int row = threadIdx.y + r * 4;
        int n = node0 + row;
        if (n < NN) {
            float v = acc[r];
            if (relu) v = fmaxf(v, 0.0f);
            out[(size_t)n * F + ox] = v;
        }
    }
}

// ---------------------------------------------------------------------------
// Launch sequence (graph-capturable: kernel launches only, default stream)
// ---------------------------------------------------------------------------
extern "C" void kernel_launch(void* const* d_in, const int* in_sizes, int n_in,
                              void* d_out, int out_size) {
    const float* x   = (const float*)d_in[0];
    const int*   ei  = (const int*)d_in[1];     // edge_index as int32 [2, E]
    const float* W1l = (const float*)d_in[2];
    const float* b1  = (const float*)d_in[3];
    const float* W1r = (const float*)d_in[4];
    const float* W2l = (const float*)d_in[5];
    const float* b2  = (const float*)d_in[6];
    const float* W2r = (const float*)d_in[7];
    float*       out = (float*)d_out;

    const int* src = ei;        // edge_index[0]
    const int* dst = ei + NE;   // edge_index[1]

    const int edgeBlocks    = (NE + 255) / 256;
    const int nodeBlocks    = (NN + 255) / 256;
    const int combineBlocks = (NN + NPB - 1) / NPB;

    // CSR build (shared by both layers)
    init_kernel<<<nodeBlocks, 256>>>();
    degree_kernel<<<edgeBlocks, 256>>>(dst);
    scan_kernel<<<1, 1024>>>();
    fill_kernel<<<edgeBlocks, 256>>>(src, dst);

    // Layer 1: x -> g_h (relu);  Layer 2: g_h -> out
    combine_kernel<<<combineBlocks, dim3(64, 4)>>>(x, W1l, b1, W1r, nullptr, 0);
    combine_kernel<<<combineBlocks, dim3(64, 4)>>>(x, W2l, b2, W2r, out, 1);
}